// round 1
// baseline (speedup 1.0000x reference)
#include <cuda_runtime.h>
#include <math.h>

// ---------------- problem dims ----------------
#define cB   256
#define cN   2048
#define cD   128
#define cR   4
#define cH   1024
#define cI   1024
#define cCI  1536
#define cIF  787
#define cOPI 1536
#define cG   4096   // 4*H

// ---------------- scratch (device globals; no allocation allowed) ----------------
__device__ float g_mean_mem[cD];          // column mean of memory (atomic target)
__device__ float g_v[cG];                 // read-part contribution to gate preacts
__device__ float g_graw[cB * cG];         // raw gate preacts (x part only)
__device__ float g_h[cB * cH];            // controller hidden
__device__ float g_itf[cB * cIF];         // raw interface (no bias)
__device__ float g_wvals[cB * cD];        // write values (raw)
__device__ float g_wvn[cB * cD];          // normalized write values
__device__ float g_erase[cB * cD];        // sigmoid(erase)
__device__ float g_wg[cB];                // write gate
__device__ float g_ag[cB];                // alloc gate
__device__ float g_rm[cB * cR * 3];       // read modes (raw -> softmaxed in place)
__device__ float g_rstr[cB * cR];         // read strengths (softplus)
__device__ float g_keys[cB * cR * cD];    // read keys raw -> normalized*str in place
__device__ float g_memn[cN * cD];         // normalized memory rows
__device__ float g_cw[cB * cN];           // content write logits -> probs
__device__ float g_alloc[cN];             // allocation weighting (before gate)
__device__ float g_ww[cB * cN];           // write weights
__device__ float g_S[cB];                 // sum_n w[b,n]
__device__ float g_t1[cN];                // sum_b w[b,m]*S[b]
__device__ float g_t2[cN];                // sum_b w[b,m]^2
__device__ float g_rowsum[cN];            // row sums of link
__device__ float g_colsum[cN];            // col sums of link (atomic target)
__device__ float g_bvec[cN];              // backward read weight vector (shared)
__device__ float g_fvec[cN];              // forward read weight vector (shared)
__device__ float g_ev[cB * cD];           // erase * write_gate
__device__ float g_av[cB * cD];           // write_vals * write_gate
__device__ float g_emat[cN * cD];         // erase matrix (raw sum over b)
__device__ float g_amat[cN * cD];         // add matrix (raw sum over b)
__device__ float g_memnew[cN * cD];       // updated memory
__device__ float g_memnewn[cN * cD];      // normalized updated memory
__device__ float g_bm[cD];                // bvec @ memnew (atomic target)
__device__ float g_fm[cD];                // fvec @ memnew (atomic target)
__device__ float g_L[cB * cR * cN];       // read content logits -> probs
__device__ float g_readc[cB * cR * cD];   // content_r @ memnew
__device__ float g_readout[cB * cR * cD]; // combined read output
__device__ float g_cat[cB * cOPI];        // [h | read_out]

// ---------------- helpers ----------------
__device__ __forceinline__ float sigmoidf_(float x) { return 1.0f / (1.0f + expf(-x)); }
__device__ __forceinline__ float softplusf_(float x) { return x > 20.0f ? x : log1pf(expf(x)); }

// ================= tiled GEMM kernels (64x64x16, 256 threads, 4x4/thread) =================
#define BM 64
#define BN 64
#define BK 16
#define SPAD 4

// C[M,Nn] = A[M,K](rm) . B[Nn,K](rm)^T  (+bias per col)
__global__ void gemm_nt(const float* __restrict__ A, int lda,
                        const float* __restrict__ Bm, int ldb,
                        const float* __restrict__ bias,
                        float* __restrict__ C, int ldc,
                        int M, int Nc, int K)
{
    __shared__ float As[BK][BM + SPAD];
    __shared__ float Bs[BK][BN + SPAD];
    const int t  = threadIdx.x;
    const int tx = t & 15, ty = t >> 4;
    const int m0 = blockIdx.y * BM, n0 = blockIdx.x * BN;
    const int ar = t >> 2, ac = (t & 3) * 4;
    float acc[4][4] = {};
    for (int k0 = 0; k0 < K; k0 += BK) {
        float4 a4 = *(const float4*)(A + (size_t)(m0 + ar) * lda + k0 + ac);
        As[ac + 0][ar] = a4.x; As[ac + 1][ar] = a4.y; As[ac + 2][ar] = a4.z; As[ac + 3][ar] = a4.w;
        int bn = n0 + ar;
        float4 b4 = make_float4(0.f, 0.f, 0.f, 0.f);
        if (bn < Nc) b4 = *(const float4*)(Bm + (size_t)bn * ldb + k0 + ac);
        Bs[ac + 0][ar] = b4.x; Bs[ac + 1][ar] = b4.y; Bs[ac + 2][ar] = b4.z; Bs[ac + 3][ar] = b4.w;
        __syncthreads();
#pragma unroll
        for (int kk = 0; kk < BK; kk++) {
            float a[4], b[4];
#pragma unroll
            for (int i = 0; i < 4; i++) { a[i] = As[kk][ty * 4 + i]; b[i] = Bs[kk][tx * 4 + i]; }
#pragma unroll
            for (int i = 0; i < 4; i++)
#pragma unroll
                for (int j = 0; j < 4; j++) acc[i][j] += a[i] * b[j];
        }
        __syncthreads();
    }
#pragma unroll
    for (int i = 0; i < 4; i++) {
        int m = m0 + ty * 4 + i;
#pragma unroll
        for (int j = 0; j < 4; j++) {
            int n = n0 + tx * 4 + j;
            if (n < Nc) C[(size_t)m * ldc + n] = acc[i][j] + (bias ? bias[n] : 0.f);
        }
    }
}

// C[M,Nn] = A[M,K](rm) . B[K,Nn](rm)
__global__ void gemm_nn(const float* __restrict__ A, int lda,
                        const float* __restrict__ Bm, int ldb,
                        float* __restrict__ C, int ldc,
                        int M, int Nc, int K)
{
    __shared__ float As[BK][BM + SPAD];
    __shared__ float Bs[BK][BN + SPAD];
    const int t  = threadIdx.x;
    const int tx = t & 15, ty = t >> 4;
    const int m0 = blockIdx.y * BM, n0 = blockIdx.x * BN;
    const int ar = t >> 2, ac = (t & 3) * 4;
    const int bk = t >> 4, bc = (t & 15) * 4;
    float acc[4][4] = {};
    for (int k0 = 0; k0 < K; k0 += BK) {
        float4 a4 = *(const float4*)(A + (size_t)(m0 + ar) * lda + k0 + ac);
        As[ac + 0][ar] = a4.x; As[ac + 1][ar] = a4.y; As[ac + 2][ar] = a4.z; As[ac + 3][ar] = a4.w;
        int bn = n0 + bc;
        if (bn + 3 < Nc) {
            float4 b4 = *(const float4*)(Bm + (size_t)(k0 + bk) * ldb + bn);
            Bs[bk][bc + 0] = b4.x; Bs[bk][bc + 1] = b4.y; Bs[bk][bc + 2] = b4.z; Bs[bk][bc + 3] = b4.w;
        } else {
#pragma unroll
            for (int i = 0; i < 4; i++)
                Bs[bk][bc + i] = (bn + i < Nc) ? Bm[(size_t)(k0 + bk) * ldb + bn + i] : 0.f;
        }
        __syncthreads();
#pragma unroll
        for (int kk = 0; kk < BK; kk++) {
            float a[4], b[4];
#pragma unroll
            for (int i = 0; i < 4; i++) { a[i] = As[kk][ty * 4 + i]; b[i] = Bs[kk][tx * 4 + i]; }
#pragma unroll
            for (int i = 0; i < 4; i++)
#pragma unroll
                for (int j = 0; j < 4; j++) acc[i][j] += a[i] * b[j];
        }
        __syncthreads();
    }
#pragma unroll
    for (int i = 0; i < 4; i++) {
        int m = m0 + ty * 4 + i;
#pragma unroll
        for (int j = 0; j < 4; j++) {
            int n = n0 + tx * 4 + j;
            if (n < Nc) C[(size_t)m * ldc + n] = acc[i][j];
        }
    }
}

// C[M,Nn] = A[K,M](rm)^T . B[K,Nn](rm)
__global__ void gemm_tn(const float* __restrict__ A, int lda,
                        const float* __restrict__ Bm, int ldb,
                        float* __restrict__ C, int ldc,
                        int M, int Nc, int K)
{
    __shared__ float As[BK][BM + SPAD];
    __shared__ float Bs[BK][BN + SPAD];
    const int t  = threadIdx.x;
    const int tx = t & 15, ty = t >> 4;
    const int m0 = blockIdx.y * BM, n0 = blockIdx.x * BN;
    const int ak = t >> 4, amc = (t & 15) * 4;
    float acc[4][4] = {};
    for (int k0 = 0; k0 < K; k0 += BK) {
        float4 a4 = *(const float4*)(A + (size_t)(k0 + ak) * lda + m0 + amc);
        As[ak][amc + 0] = a4.x; As[ak][amc + 1] = a4.y; As[ak][amc + 2] = a4.z; As[ak][amc + 3] = a4.w;
        int bn = n0 + amc;
        if (bn + 3 < Nc) {
            float4 b4 = *(const float4*)(Bm + (size_t)(k0 + ak) * ldb + bn);
            Bs[ak][amc + 0] = b4.x; Bs[ak][amc + 1] = b4.y; Bs[ak][amc + 2] = b4.z; Bs[ak][amc + 3] = b4.w;
        } else {
#pragma unroll
            for (int i = 0; i < 4; i++)
                Bs[ak][amc + i] = (bn + i < Nc) ? Bm[(size_t)(k0 + ak) * ldb + bn + i] : 0.f;
        }
        __syncthreads();
#pragma unroll
        for (int kk = 0; kk < BK; kk++) {
            float a[4], b[4];
#pragma unroll
            for (int i = 0; i < 4; i++) { a[i] = As[kk][ty * 4 + i]; b[i] = Bs[kk][tx * 4 + i]; }
#pragma unroll
            for (int i = 0; i < 4; i++)
#pragma unroll
                for (int j = 0; j < 4; j++) acc[i][j] += a[i] * b[j];
        }
        __syncthreads();
    }
#pragma unroll
    for (int i = 0; i < 4; i++) {
        int m = m0 + ty * 4 + i;
#pragma unroll
        for (int j = 0; j < 4; j++) {
            int n = n0 + tx * 4 + j;
            if (n < Nc) C[(size_t)m * ldc + n] = acc[i][j];
        }
    }
}

// ================= small kernels =================

// column mean of memory (N x D) -> g_mean_mem (atomic accumulate, pre-zeroed)
__global__ void k_mem_mean(const float* __restrict__ memory) {
    int t = threadIdx.x;              // 128 threads = d
    int r0 = blockIdx.x * 64;         // 32 blocks
    float s = 0.f;
    for (int r = 0; r < 64; r++) s += memory[(size_t)(r0 + r) * cD + t];
    atomicAdd(&g_mean_mem[t], s * (1.0f / (float)cN));
}

// v[j] = sum_{k<512} mean_mem[k%128] * W_ih[j, 1024+k]   (one warp per j)
__global__ void k_v(const float* __restrict__ W_ih) {
    int gw = (blockIdx.x * blockDim.x + threadIdx.x) >> 5;
    int lane = threadIdx.x & 31;
    if (gw >= cG) return;
    const float* wr = W_ih + (size_t)gw * cCI + cI;
    float a = 0.f;
    for (int k = lane; k < cR * cD; k += 32) a += g_mean_mem[k & (cD - 1)] * wr[k];
#pragma unroll
    for (int o = 16; o > 0; o >>= 1) a += __shfl_xor_sync(0xffffffffu, a, o);
    if (lane == 0) g_v[gw] = a;
}

// row/col sums of link (N x N); colsum atomically accumulated (pre-zeroed)
__global__ void k_linksums(const float* __restrict__ link) {
    __shared__ float red[256];
    int t = threadIdx.x;
    float colacc[8];
#pragma unroll
    for (int i = 0; i < 8; i++) colacc[i] = 0.f;
    int r0 = blockIdx.x * 32;
    for (int r = 0; r < 32; r++) {
        const float* row = link + (size_t)(r0 + r) * cN;
        float rs = 0.f;
#pragma unroll
        for (int i = 0; i < 8; i++) { float v = row[t + i * 256]; rs += v; colacc[i] += v; }
        red[t] = rs; __syncthreads();
        for (int o = 128; o > 0; o >>= 1) { if (t < o) red[t] += red[t + o]; __syncthreads(); }
        if (t == 0) g_rowsum[r0 + r] = red[0];
        __syncthreads();
    }
#pragma unroll
    for (int i = 0; i < 8; i++) atomicAdd(&g_colsum[t + i * 256], colacc[i]);
}

// LSTM gates: h = sigmoid(o)*tanh(sigmoid(i)*tanh(g))
__global__ void k_gates(const float* __restrict__ b_ih, const float* __restrict__ b_hh) {
    int idx = blockIdx.x * blockDim.x + threadIdx.x;  // B*H
    if (idx >= cB * cH) return;
    int b = idx >> 10, j = idx & (cH - 1);
    const float* gr = g_graw + (size_t)b * cG;
    float gi = gr[j]            + b_ih[j]            + b_hh[j]            + g_v[j];
    float gg = gr[j + 2 * cH]   + b_ih[j + 2 * cH]   + b_hh[j + 2 * cH]   + g_v[j + 2 * cH];
    float go = gr[j + 3 * cH]   + b_ih[j + 3 * cH]   + b_hh[j + 3 * cH]   + g_v[j + 3 * cH];
    float c = sigmoidf_(gi) * tanhf(gg);
    g_h[idx] = sigmoidf_(go) * tanhf(c);
}

// parse interface vector
__global__ void k_parse(const float* __restrict__ b_if) {
    int idx = blockIdx.x * blockDim.x + threadIdx.x;
    if (idx >= cB * cIF) return;
    int b = idx / cIF, j = idx - b * cIF;
    float val = g_itf[idx] + b_if[j];
    if (j < 128)       g_wvals[b * cD + j] = val;
    else if (j < 256)  g_erase[b * cD + (j - 128)] = sigmoidf_(val);
    else if (j == 256) g_wg[b] = sigmoidf_(val);
    else if (j == 257) g_ag[b] = sigmoidf_(val);
    else if (j == 258) { /* free gate, unused */ }
    else if (j < 271)  g_rm[b * 12 + (j - 259)] = val;
    else if (j < 275)  g_rstr[b * cR + (j - 271)] = softplusf_(val);
    else               g_keys[b * cR * cD + (j - 275)] = val;
}

// softmax over 3 read modes
__global__ void k_softmax3() {
    int idx = blockIdx.x * blockDim.x + threadIdx.x;  // B*R
    if (idx >= cB * cR) return;
    float* p = g_rm + idx * 3;
    float m = fmaxf(p[0], fmaxf(p[1], p[2]));
    float e0 = expf(p[0] - m), e1 = expf(p[1] - m), e2 = expf(p[2] - m);
    float inv = 1.0f / (e0 + e1 + e2);
    p[0] = e0 * inv; p[1] = e1 * inv; p[2] = e2 * inv;
}

// normalize 128-wide rows: Y = X/max(||X||,eps) * (scale?scale[row]:1)   (in-place safe)
__global__ void k_rownorm(const float* __restrict__ X, float* __restrict__ Y,
                          const float* __restrict__ scale) {
    int row = blockIdx.x, t = threadIdx.x;  // 128 threads
    float v = X[(size_t)row * cD + t];
    float sq = v * v;
#pragma unroll
    for (int o = 16; o > 0; o >>= 1) sq += __shfl_xor_sync(0xffffffffu, sq, o);
    __shared__ float sh[4];
    if ((t & 31) == 0) sh[t >> 5] = sq;
    __syncthreads();
    float total = sh[0] + sh[1] + sh[2] + sh[3];
    float denom = fmaxf(sqrtf(total), 1e-12f);
    float sc = scale ? scale[row] : 1.0f;
    Y[(size_t)row * cD + t] = v / denom * sc;
}

// row softmax over 2048 columns (in place), one block per row
__global__ void k_softmax2048(float* __restrict__ X) {
    float* p = X + (size_t)blockIdx.x * cN;
    int t = threadIdx.x;  // 256
    float v[8];
    float mx = -3.4e38f;
#pragma unroll
    for (int i = 0; i < 8; i++) { v[i] = p[t + 256 * i]; mx = fmaxf(mx, v[i]); }
#pragma unroll
    for (int o = 16; o > 0; o >>= 1) mx = fmaxf(mx, __shfl_xor_sync(0xffffffffu, mx, o));
    __shared__ float sh[8];
    __shared__ float bc;
    if ((t & 31) == 0) sh[t >> 5] = mx;
    __syncthreads();
    if (t == 0) { float m = sh[0]; for (int i = 1; i < 8; i++) m = fmaxf(m, sh[i]); bc = m; }
    __syncthreads();
    mx = bc;
    float s = 0.f;
#pragma unroll
    for (int i = 0; i < 8; i++) { v[i] = expf(v[i] - mx); s += v[i]; }
#pragma unroll
    for (int o = 16; o > 0; o >>= 1) s += __shfl_xor_sync(0xffffffffu, s, o);
    __syncthreads();
    if ((t & 31) == 0) sh[t >> 5] = s;
    __syncthreads();
    if (t == 0) { float m = 0.f; for (int i = 0; i < 8; i++) m += sh[i]; bc = m; }
    __syncthreads();
    float inv = 1.0f / bc;
#pragma unroll
    for (int i = 0; i < 8; i++) p[t + 256 * i] = v[i] * inv;
}

// allocation weighting: single block, bitonic sort + cumprod scan
__global__ void k_alloc(const float* __restrict__ usage) {
    __shared__ float sv[cN];
    __shared__ int   si[cN];
    __shared__ float cp[cN];
    __shared__ float cq[cN];
    int t = threadIdx.x;  // 1024
    sv[t] = usage[t]; sv[t + 1024] = usage[t + 1024];
    si[t] = t; si[t + 1024] = t + 1024;
    __syncthreads();
    for (int k = 2; k <= cN; k <<= 1) {
        for (int j = k >> 1; j > 0; j >>= 1) {
#pragma unroll
            for (int s = 0; s < 2; s++) {
                int i = t + s * 1024;
                int ixj = i ^ j;
                if (ixj > i) {
                    bool up = ((i & k) == 0);
                    float a = sv[i], b = sv[ixj];
                    if ((a > b) == up) {
                        sv[i] = b; sv[ixj] = a;
                        int tmp = si[i]; si[i] = si[ixj]; si[ixj] = tmp;
                    }
                }
            }
            __syncthreads();
        }
    }
    cp[t] = 1.0f - sv[t]; cp[t + 1024] = 1.0f - sv[t + 1024];
    __syncthreads();
    float* src = cp; float* dst = cq;
    for (int off = 1; off < cN; off <<= 1) {
#pragma unroll
        for (int s = 0; s < 2; s++) {
            int i = t + s * 1024;
            dst[i] = src[i] * (i >= off ? src[i - off] : 1.0f);
        }
        __syncthreads();
        float* tmp = src; src = dst; dst = tmp;
    }
#pragma unroll
    for (int s = 0; s < 2; s++) {
        int i = t + s * 1024;
        float as = (i == 0) ? sv[0] : sv[i] * src[i - 1];
        g_alloc[si[i]] = as;
    }
}

// write weights: w[b,n] = wg[b]*(0.5*cw[b,n] + 0.5*alloc[n]*ag[b])
__global__ void k_writew() {
    int idx = blockIdx.x * blockDim.x + threadIdx.x;  // B*N
    if (idx >= cB * cN) return;
    int b = idx >> 11, n = idx & (cN - 1);
    g_ww[idx] = g_wg[b] * (0.5f * g_cw[idx] + 0.5f * g_alloc[n] * g_ag[b]);
}

// S[b] = sum_n w[b,n]  (block per b)
__global__ void k_S() {
    int b = blockIdx.x, t = threadIdx.x;  // 256
    float s = 0.f;
#pragma unroll
    for (int i = 0; i < 8; i++) s += g_ww[(size_t)b * cN + t + i * 256];
#pragma unroll
    for (int o = 16; o > 0; o >>= 1) s += __shfl_xor_sync(0xffffffffu, s, o);
    __shared__ float sh[8];
    if ((t & 31) == 0) sh[t >> 5] = s;
    __syncthreads();
    if (t == 0) { float m = 0.f; for (int i = 0; i < 8; i++) m += sh[i]; g_S[b] = m; }
}

// t1[m] = sum_b w[b,m]*S[b];  t2[m] = sum_b w[b,m]^2
__global__ void k_t12() {
    int m = blockIdx.x * blockDim.x + threadIdx.x;
    if (m >= cN) return;
    float t1 = 0.f, t2 = 0.f;
    for (int b = 0; b < cB; b++) {
        float w = g_ww[(size_t)b * cN + m];
        t1 += w * g_S[b];
        t2 += w * w;
    }
    g_t1[m] = t1; g_t2[m] = t2;
}

// backward/forward shared read vectors
__global__ void k_bfvec() {
    int m = blockIdx.x * blockDim.x + threadIdx.x;
    if (m >= cN) return;
    float lu = 0.1f * (g_t1[m] - g_t2[m]) * (1.0f / (float)cB);
    g_bvec[m] = (0.9f * g_colsum[m] + lu) * (1.0f / (float)cN);
    g_fvec[m] = (0.9f * g_rowsum[m] + lu) * (1.0f / (float)cN);
}

// ev = erase*wg, av = wvals*wg
__global__ void k_evav() {
    int idx = blockIdx.x * blockDim.x + threadIdx.x;  // B*D
    if (idx >= cB * cD) return;
    int b = idx >> 7;
    float w = g_wg[b];
    g_ev[idx] = g_erase[idx] * w;
    g_av[idx] = g_wvals[idx] * w;
}

// mem_new = memory*(1 - emat/B) + amat/B
__global__ void k_memupdate(const float* __restrict__ memory) {
    int idx = blockIdx.x * blockDim.x + threadIdx.x;
    if (idx >= cN * cD) return;
    const float inv = 1.0f / (float)cB;
    g_memnew[idx] = memory[idx] * (1.0f - g_emat[idx] * inv) + g_amat[idx] * inv;
}

// bm = bvec @ memnew, fm = fvec @ memnew (atomic accumulate, pre-zeroed)
__global__ void k_bmfm() {
    int t = threadIdx.x;        // 128 = d
    int r0 = blockIdx.x * 64;   // 32 blocks
    float sb = 0.f, sf = 0.f;
    for (int r = 0; r < 64; r++) {
        float m = g_memnew[(size_t)(r0 + r) * cD + t];
        sb += g_bvec[r0 + r] * m;
        sf += g_fvec[r0 + r] * m;
    }
    atomicAdd(&g_bm[t], sb);
    atomicAdd(&g_fm[t], sf);
}

// read_out = rm0*read_c + rm1*bm + rm2*fm
__global__ void k_readout() {
    int idx = blockIdx.x * blockDim.x + threadIdx.x;  // B*R*D
    if (idx >= cB * cR * cD) return;
    int br = idx >> 7, d = idx & (cD - 1);
    const float* rm = g_rm + br * 3;
    g_readout[idx] = rm[0] * g_readc[idx] + rm[1] * g_bm[d] + rm[2] * g_fm[d];
}

// cat = [h | read_out]
__global__ void k_cat() {
    int idx = blockIdx.x * blockDim.x + threadIdx.x;  // B*OPI
    if (idx >= cB * cOPI) return;
    int b = idx / cOPI, j = idx - b * cOPI;
    g_cat[idx] = (j < cH) ? g_h[(size_t)b * cH + j]
                          : g_readout[(size_t)b * (cR * cD) + (j - cH)];
}

// ================= host launch =================
static void* symaddr(const void* sym) { void* p = nullptr; cudaGetSymbolAddress(&p, sym); return p; }

extern "C" void kernel_launch(void* const* d_in, const int* in_sizes, int n_in,
                              void* d_out, int out_size) {
    const float* x      = (const float*)d_in[0];
    const float* memory = (const float*)d_in[1];
    const float* usage  = (const float*)d_in[2];
    const float* link   = (const float*)d_in[3];
    const float* W_ih   = (const float*)d_in[4];
    // d_in[5] = W_hh (unused: h0 = 0)
    const float* b_ih   = (const float*)d_in[6];
    const float* b_hh   = (const float*)d_in[7];
    const float* W_if   = (const float*)d_in[8];
    const float* b_if   = (const float*)d_in[9];
    const float* W_out  = (const float*)d_in[10];
    const float* b_out  = (const float*)d_in[11];
    float* out = (float*)d_out;

    float* p_graw    = (float*)symaddr(g_graw);
    float* p_h       = (float*)symaddr(g_h);
    float* p_itf     = (float*)symaddr(g_itf);
    float* p_wvn     = (float*)symaddr(g_wvn);
    float* p_wvals   = (float*)symaddr(g_wvals);
    float* p_memn    = (float*)symaddr(g_memn);
    float* p_cw      = (float*)symaddr(g_cw);
    float* p_ww      = (float*)symaddr(g_ww);
    float* p_ev      = (float*)symaddr(g_ev);
    float* p_av      = (float*)symaddr(g_av);
    float* p_emat    = (float*)symaddr(g_emat);
    float* p_amat    = (float*)symaddr(g_amat);
    float* p_memnew  = (float*)symaddr(g_memnew);
    float* p_memnewn = (float*)symaddr(g_memnewn);
    float* p_keys    = (float*)symaddr(g_keys);
    float* p_rstr    = (float*)symaddr(g_rstr);
    float* p_L       = (float*)symaddr(g_L);
    float* p_readc   = (float*)symaddr(g_readc);
    float* p_cat     = (float*)symaddr(g_cat);
    float* p_meanm   = (float*)symaddr(g_mean_mem);
    float* p_colsum  = (float*)symaddr(g_colsum);
    float* p_bm      = (float*)symaddr(g_bm);
    float* p_fm      = (float*)symaddr(g_fm);

    // zero atomic accumulators (every call — deterministic)
    cudaMemsetAsync(p_meanm, 0, cD * sizeof(float));
    cudaMemsetAsync(p_colsum, 0, cN * sizeof(float));
    cudaMemsetAsync(p_bm, 0, cD * sizeof(float));
    cudaMemsetAsync(p_fm, 0, cD * sizeof(float));

    // stage 0: independent precomputation
    k_mem_mean<<<32, 128>>>(memory);
    k_rownorm<<<cN, 128>>>(memory, p_memn, nullptr);
    k_linksums<<<64, 256>>>(link);
    k_alloc<<<1, 1024>>>(usage);
    k_v<<<512, 256>>>(W_ih);

    // controller LSTM
    gemm_nt<<<dim3(cG / 64, cB / 64), 256>>>(x, cI, W_ih, cCI, nullptr, p_graw, cG, cB, cG, cI);
    k_gates<<<(cB * cH + 255) / 256, 256>>>(b_ih, b_hh);

    // interface
    gemm_nt<<<dim3((cIF + 63) / 64, cB / 64), 256>>>(p_h, cH, W_if, cH, nullptr, p_itf, cIF, cB, cIF, cH);
    k_parse<<<(cB * cIF + 255) / 256, 256>>>(b_if);
    k_softmax3<<<(cB * cR + 255) / 256, 256>>>();
    k_rownorm<<<cB, 128>>>(p_wvals, p_wvn, nullptr);
    k_rownorm<<<cB * cR, 128>>>(p_keys, p_keys, p_rstr);

    // content write addressing
    gemm_nt<<<dim3(cN / 64, cB / 64), 256>>>(p_wvn, cD, p_memn, cD, nullptr, p_cw, cN, cB, cN, cD);
    k_softmax2048<<<cB, 256>>>(p_cw);

    // write weights + link-mean statistics
    k_writew<<<(cB * cN + 255) / 256, 256>>>();
    k_S<<<cB, 256>>>();
    k_t12<<<(cN + 255) / 256, 256>>>();
    k_bfvec<<<(cN + 255) / 256, 256>>>();

    // memory update
    k_evav<<<(cB * cD + 255) / 256, 256>>>();
    gemm_tn<<<dim3(cD / 64, cN / 64), 256>>>(p_ww, cN, p_ev, cD, p_emat, cD, cN, cD, cB);
    gemm_tn<<<dim3(cD / 64, cN / 64), 256>>>(p_ww, cN, p_av, cD, p_amat, cD, cN, cD, cB);
    k_memupdate<<<(cN * cD + 255) / 256, 256>>>(memory);
    k_rownorm<<<cN, 128>>>(p_memnew, p_memnewn, nullptr);
    k_bmfm<<<32, 128>>>();

    // read addressing
    gemm_nt<<<dim3(cN / 64, (cB * cR) / 64), 256>>>(p_keys, cD, p_memnewn, cD, nullptr, p_L, cN, cB * cR, cN, cD);
    k_softmax2048<<<cB * cR, 256>>>(p_L);
    gemm_nn<<<dim3(cD / 64, (cB * cR) / 64), 256>>>(p_L, cN, p_memnew, cD, p_readc, cD, cB * cR, cD, cN);
    k_readout<<<(cB * cR * cD + 255) / 256, 256>>>();

    // output projection
    k_cat<<<(cB * cOPI + 255) / 256, 256>>>();
    gemm_nt<<<dim3(cH / 64, cB / 64), 256>>>(p_cat, cOPI, W_out, cOPI, b_out, out, cH, cB, cH, cOPI);
}